// round 2
// baseline (speedup 1.0000x reference)
#include <cuda_runtime.h>

// ---------------------------------------------------------------------------
// SwinTransformerBlock3D: DIM=96, HEADS=6, hd=16, WIN=4x4x4 (N=64), SHIFT=2,
// GRID=(16,64,64), B=2.  Cyclic shift == index remap (no mask in reference).
// ---------------------------------------------------------------------------

#define NWIN 2048          // B * (16/4)*(64/4)*(64/4)
#define NTOK 131072        // B * L
#define DIMC 96
#define HP 97              // padded row stride (conflict-free A-operand reads)

// Scratch (static device globals; no allocations allowed)
__device__ float g_q [NWIN * 64 * DIMC];   // [win][n][head*16+d]
__device__ float g_k [NWIN * 64 * DIMC];
__device__ float g_v [NWIN * 64 * DIMC];
__device__ float g_ow[NWIN * 64 * DIMC];   // attention output per window
__device__ float g_x1[NTOK * DIMC];        // x + proj(attn)  (first residual)

// ---------------------------------------------------------------------------
// K1: LN1 + cyclic-shift gather + window partition + QKV GEMM (64x288, K=96)
// one block per window, 128 threads
// ---------------------------------------------------------------------------
__global__ __launch_bounds__(128) void k1_ln_qkv(
    const float* __restrict__ x,
    const float* __restrict__ g1, const float* __restrict__ b1,
    const float* __restrict__ qkvw, const float* __restrict__ qkvb)
{
    __shared__ float hs[64 * HP];    // LN'd window tokens, padded stride
    __shared__ float ws[96 * 48];    // weight chunk [96][48]

    const int tid  = threadIdx.x;
    const int lane = tid & 31;
    const int wrp  = tid >> 5;
    const int win  = blockIdx.x;
    const int b  = win >> 10;
    const int r  = win & 1023;
    const int wi = r >> 8, wx = (r >> 4) & 15, wt = r & 15;

    const float gv0 = g1[lane], gv1 = g1[lane + 32], gv2 = g1[lane + 64];
    const float bb0 = b1[lane], bb1 = b1[lane + 32], bb2 = b1[lane + 64];

    // LN + gather: each warp handles 16 rows
    for (int j = 0; j < 16; j++) {
        const int n  = wrp * 16 + j;
        const int ii = n >> 4, xx = (n >> 2) & 3, tt = n & 3;
        const int gi = (wi * 4 + ii + 2) & 15;
        const int gx = (wx * 4 + xx + 2) & 63;
        const int gt = (wt * 4 + tt + 2) & 63;
        const int tok = b * 65536 + (gi * 64 + gx) * 64 + gt;
        const float* row = x + tok * 96;
        float v0 = row[lane], v1 = row[lane + 32], v2 = row[lane + 64];
        float s = v0 + v1 + v2;
        float q = v0 * v0 + v1 * v1 + v2 * v2;
        #pragma unroll
        for (int o = 16; o > 0; o >>= 1) {
            s += __shfl_xor_sync(0xffffffffu, s, o);
            q += __shfl_xor_sync(0xffffffffu, q, o);
        }
        const float mean = s * (1.0f / 96.0f);
        const float var  = q * (1.0f / 96.0f) - mean * mean;
        const float rstd = rsqrtf(var + 1e-5f);
        hs[n * HP + lane]      = (v0 - mean) * rstd * gv0 + bb0;
        hs[n * HP + lane + 32] = (v1 - mean) * rstd * gv1 + bb1;
        hs[n * HP + lane + 64] = (v2 - mean) * rstd * gv2 + bb2;
    }
    __syncthreads();

    // GEMM: 6 column chunks of 48 (q0,q1,k0,k1,v0,v1)
    const int rg = tid >> 3;   // 0..15  -> rows rg*4..+4
    const int cg = tid & 7;    // 0..7   -> cols cg*6..+6
    const int r0 = rg * 4, c0 = cg * 6;

    for (int cc = 0; cc < 6; cc++) {
        const int colbase = cc * 48;
        for (int idx = tid; idx < 1152; idx += 128) {
            const int row = idx / 12, c4 = idx % 12;
            *(float4*)&ws[row * 48 + c4 * 4] =
                *(const float4*)(qkvw + row * 288 + colbase + c4 * 4);
        }
        __syncthreads();

        float acc[4][6];
        #pragma unroll
        for (int i = 0; i < 4; i++)
            #pragma unroll
            for (int j = 0; j < 6; j++) acc[i][j] = 0.0f;

        #pragma unroll 4
        for (int k = 0; k < 96; k++) {
            const float a0 = hs[(r0 + 0) * HP + k];
            const float a1 = hs[(r0 + 1) * HP + k];
            const float a2 = hs[(r0 + 2) * HP + k];
            const float a3 = hs[(r0 + 3) * HP + k];
            const float* wr = &ws[k * 48 + c0];
            #pragma unroll
            for (int j = 0; j < 6; j++) {
                const float w = wr[j];
                acc[0][j] += a0 * w;
                acc[1][j] += a1 * w;
                acc[2][j] += a2 * w;
                acc[3][j] += a3 * w;
            }
        }

        float* dst = (cc < 2) ? g_q : (cc < 4) ? g_k : g_v;
        const int cb = (cc & 1) * 48;
        #pragma unroll
        for (int i = 0; i < 4; i++) {
            float* drow = dst + (win * 64 + r0 + i) * 96 + cb + c0;
            #pragma unroll
            for (int j = 0; j < 6; j++)
                drow[j] = acc[i][j] + qkvb[colbase + c0 + j];
        }
        __syncthreads();
    }
}

// ---------------------------------------------------------------------------
// K2: windowed attention, one block per (window, head), 64 threads (1 row ea.)
// bias computed on the fly from relative coords; scores in padded smem rows
// ---------------------------------------------------------------------------
__global__ __launch_bounds__(64) void k2_attn(const float* __restrict__ btab)
{
    __shared__ float4 sq[64 * 4], sk[64 * 4], sv[64 * 4];
    __shared__ float  ss[64 * 65];     // padded score rows (conflict-free)
    __shared__ float  stab[343 * 6];

    const int n    = threadIdx.x;
    const int win  = blockIdx.x / 6;
    const int head = blockIdx.x % 6;
    const int base = win * 64 * 96 + head * 16;

    #pragma unroll
    for (int j = 0; j < 4; j++) {
        sq[n * 4 + j] = ((const float4*)(g_q + base + n * 96))[j];
        sk[n * 4 + j] = ((const float4*)(g_k + base + n * 96))[j];
        sv[n * 4 + j] = ((const float4*)(g_v + base + n * 96))[j];
    }
    for (int i = n; i < 2058; i += 64) stab[i] = btab[i];
    __syncthreads();

    const float4 q0 = sq[n * 4 + 0], q1 = sq[n * 4 + 1];
    const float4 q2 = sq[n * 4 + 2], q3 = sq[n * 4 + 3];
    const int iin = n >> 4, xn = (n >> 2) & 3, tn = n & 3;
    float* myrow = &ss[n * 65];

    #pragma unroll 8
    for (int m = 0; m < 64; m++) {
        const float4 k0 = sk[m * 4 + 0], k1 = sk[m * 4 + 1];
        const float4 k2 = sk[m * 4 + 2], k3 = sk[m * 4 + 3];
        float s = q0.x * k0.x + q0.y * k0.y + q0.z * k0.z + q0.w * k0.w
                + q1.x * k1.x + q1.y * k1.y + q1.z * k1.z + q1.w * k1.w
                + q2.x * k2.x + q2.y * k2.y + q2.z * k2.z + q2.w * k2.w
                + q3.x * k3.x + q3.y * k3.y + q3.z * k3.z + q3.w * k3.w;
        const int im = m >> 4, xm = (m >> 2) & 3, tm = m & 3;
        const int rel = ((iin - im + 3) * 7 + (xn - xm + 3)) * 7 + (tn - tm + 3);
        myrow[m] = s * 0.25f + stab[rel * 6 + head];
    }

    float mx = -1e30f;
    #pragma unroll
    for (int m = 0; m < 64; m++) mx = fmaxf(mx, myrow[m]);
    float sum = 0.0f;
    #pragma unroll 8
    for (int m = 0; m < 64; m++) {
        const float p = __expf(myrow[m] - mx);
        myrow[m] = p;
        sum += p;
    }
    const float inv = 1.0f / sum;

    float4 o0 = {0,0,0,0}, o1 = {0,0,0,0}, o2 = {0,0,0,0}, o3 = {0,0,0,0};
    #pragma unroll 8
    for (int m = 0; m < 64; m++) {
        const float p = myrow[m];
        const float4 v0 = sv[m * 4 + 0], v1 = sv[m * 4 + 1];
        const float4 v2 = sv[m * 4 + 2], v3 = sv[m * 4 + 3];
        o0.x += p * v0.x; o0.y += p * v0.y; o0.z += p * v0.z; o0.w += p * v0.w;
        o1.x += p * v1.x; o1.y += p * v1.y; o1.z += p * v1.z; o1.w += p * v1.w;
        o2.x += p * v2.x; o2.y += p * v2.y; o2.z += p * v2.z; o2.w += p * v2.w;
        o3.x += p * v3.x; o3.y += p * v3.y; o3.z += p * v3.z; o3.w += p * v3.w;
    }
    float4* od = (float4*)(g_ow + base + n * 96);
    o0.x *= inv; o0.y *= inv; o0.z *= inv; o0.w *= inv;
    o1.x *= inv; o1.y *= inv; o1.z *= inv; o1.w *= inv;
    o2.x *= inv; o2.y *= inv; o2.z *= inv; o2.w *= inv;
    o3.x *= inv; o3.y *= inv; o3.z *= inv; o3.w *= inv;
    od[0] = o0; od[1] = o1; od[2] = o2; od[3] = o3;
}

// ---------------------------------------------------------------------------
// K3: proj GEMM (64x96, K=96) + window reverse + un-shift scatter + residual
// one block per window, 128 threads
// ---------------------------------------------------------------------------
__global__ __launch_bounds__(128) void k3_proj(
    const float* __restrict__ x,
    const float* __restrict__ pw, const float* __restrict__ pb)
{
    __shared__ float os[64 * HP];
    __shared__ float ws[96 * 48];

    const int tid = threadIdx.x;
    const int win = blockIdx.x;

    // load 64x96 window output into padded smem (float4 gmem reads)
    for (int idx = tid; idx < 1536; idx += 128) {
        const float4 v = ((const float4*)(g_ow + win * 64 * 96))[idx];
        const int row = idx / 24, c4 = idx % 24;   // 24 float4 per 96-col row
        float* d = &os[row * HP + c4 * 4];
        d[0] = v.x; d[1] = v.y; d[2] = v.z; d[3] = v.w;
    }

    const int b = win >> 10, r = win & 1023;
    const int wi = r >> 8, wx = (r >> 4) & 15, wt = r & 15;
    const int rg = tid >> 3, cg = tid & 7;
    const int r0 = rg * 4, c0 = cg * 6;

    int tok[4];
    #pragma unroll
    for (int i = 0; i < 4; i++) {
        const int n = r0 + i;
        const int ii = n >> 4, xx = (n >> 2) & 3, tt = n & 3;
        const int gi = (wi * 4 + ii + 2) & 15;
        const int gx = (wx * 4 + xx + 2) & 63;
        const int gt = (wt * 4 + tt + 2) & 63;
        tok[i] = b * 65536 + (gi * 64 + gx) * 64 + gt;
    }
    __syncthreads();

    for (int cc = 0; cc < 2; cc++) {
        const int colbase = cc * 48;
        for (int idx = tid; idx < 1152; idx += 128) {
            const int row = idx / 12, c4 = idx % 12;
            *(float4*)&ws[row * 48 + c4 * 4] =
                *(const float4*)(pw + row * 96 + colbase + c4 * 4);
        }
        __syncthreads();

        float acc[4][6];
        #pragma unroll
        for (int i = 0; i < 4; i++)
            #pragma unroll
            for (int j = 0; j < 6; j++) acc[i][j] = 0.0f;

        #pragma unroll 4
        for (int k = 0; k < 96; k++) {
            const float a0 = os[(r0 + 0) * HP + k];
            const float a1 = os[(r0 + 1) * HP + k];
            const float a2 = os[(r0 + 2) * HP + k];
            const float a3 = os[(r0 + 3) * HP + k];
            const float* wr = &ws[k * 48 + c0];
            #pragma unroll
            for (int j = 0; j < 6; j++) {
                const float w = wr[j];
                acc[0][j] += a0 * w;
                acc[1][j] += a1 * w;
                acc[2][j] += a2 * w;
                acc[3][j] += a3 * w;
            }
        }

        #pragma unroll
        for (int i = 0; i < 4; i++) {
            const float* xr = x + tok[i] * 96 + colbase + c0;
            float* dr = g_x1 + tok[i] * 96 + colbase + c0;
            #pragma unroll
            for (int j = 0; j < 6; j++)
                dr[j] = xr[j] + acc[i][j] + pb[colbase + c0 + j];
        }
        __syncthreads();
    }
}

// ---------------------------------------------------------------------------
// K4: LN2 + MLP (96->384 GELU -> 96) + residual, fused. 32 tokens per block,
// 128 threads. Weights streamed through a 48-wide smem chunk buffer.
// ---------------------------------------------------------------------------
__global__ __launch_bounds__(128) void k4_mlp(
    const float* __restrict__ g2, const float* __restrict__ b2,
    const float* __restrict__ w1, const float* __restrict__ b1m,
    const float* __restrict__ w2, const float* __restrict__ b2m,
    float* __restrict__ out)
{
    __shared__ float xs[32 * HP];
    __shared__ float hidc[32 * HP];
    __shared__ float ws[96 * 48];

    const int tid  = threadIdx.x;
    const int lane = tid & 31;
    const int wrp  = tid >> 5;
    const int t0   = blockIdx.x * 32;

    const float gv0 = g2[lane], gv1 = g2[lane + 32], gv2 = g2[lane + 64];
    const float bb0 = b2[lane], bb1 = b2[lane + 32], bb2 = b2[lane + 64];

    for (int j = 0; j < 8; j++) {
        const int rrow = wrp * 8 + j;
        const float* row = g_x1 + (t0 + rrow) * 96;
        float v0 = row[lane], v1 = row[lane + 32], v2 = row[lane + 64];
        float s = v0 + v1 + v2;
        float q = v0 * v0 + v1 * v1 + v2 * v2;
        #pragma unroll
        for (int o = 16; o > 0; o >>= 1) {
            s += __shfl_xor_sync(0xffffffffu, s, o);
            q += __shfl_xor_sync(0xffffffffu, q, o);
        }
        const float mean = s * (1.0f / 96.0f);
        const float var  = q * (1.0f / 96.0f) - mean * mean;
        const float rstd = rsqrtf(var + 1e-5f);
        xs[rrow * HP + lane]      = (v0 - mean) * rstd * gv0 + bb0;
        xs[rrow * HP + lane + 32] = (v1 - mean) * rstd * gv1 + bb1;
        xs[rrow * HP + lane + 64] = (v2 - mean) * rstd * gv2 + bb2;
    }
    __syncthreads();

    const int rgO = tid >> 4;       // 0..7 -> rows rgO*4
    const int cgO = tid & 15;       // 0..15
    const int r0 = rgO * 4;

    float acc[4][6];
    #pragma unroll
    for (int i = 0; i < 4; i++)
        #pragma unroll
        for (int j = 0; j < 6; j++) acc[i][j] = 0.0f;

    for (int hc = 0; hc < 4; hc++) {
        // Phase A: hidc[32][96] = gelu(xs @ w1[:, hc*96 : hc*96+96] + b1)
        for (int sub = 0; sub < 2; sub++) {
            const int hbase = hc * 96 + sub * 48;
            for (int idx = tid; idx < 1152; idx += 128) {
                const int row = idx / 12, c4 = idx % 12;
                *(float4*)&ws[row * 48 + c4 * 4] =
                    *(const float4*)(w1 + row * 384 + hbase + c4 * 4);
            }
            __syncthreads();

            const int hc0 = cgO * 3;
            float ah[4][3];
            #pragma unroll
            for (int i = 0; i < 4; i++)
                #pragma unroll
                for (int j = 0; j < 3; j++) ah[i][j] = 0.0f;

            #pragma unroll 4
            for (int k = 0; k < 96; k++) {
                const float a0 = xs[(r0 + 0) * HP + k];
                const float a1 = xs[(r0 + 1) * HP + k];
                const float a2 = xs[(r0 + 2) * HP + k];
                const float a3 = xs[(r0 + 3) * HP + k];
                const float* wr = &ws[k * 48 + hc0];
                #pragma unroll
                for (int j = 0; j < 3; j++) {
                    const float w = wr[j];
                    ah[0][j] += a0 * w;
                    ah[1][j] += a1 * w;
                    ah[2][j] += a2 * w;
                    ah[3][j] += a3 * w;
                }
            }
            #pragma unroll
            for (int i = 0; i < 4; i++)
                #pragma unroll
                for (int j = 0; j < 3; j++) {
                    const float h = ah[i][j] + b1m[hbase + hc0 + j];
                    hidc[(r0 + i) * HP + sub * 48 + hc0 + j] =
                        0.5f * h * (1.0f + erff(h * 0.70710678118654752f));
                }
            __syncthreads();
        }

        // Phase B: acc += hidc @ w2[hc*96 : hc*96+96, :]
        for (int ksub = 0; ksub < 2; ksub++) {
            const int kb = hc * 96 + ksub * 48;
            for (int idx = tid; idx < 1152; idx += 128) {
                const int row = idx / 24, c4 = idx % 24;   // ws as [48][96]
                *(float4*)&ws[row * 96 + c4 * 4] =
                    *(const float4*)(w2 + (kb + row) * 96 + c4 * 4);
            }
            __syncthreads();

            const int c0 = cgO * 6;
            #pragma unroll 4
            for (int k = 0; k < 48; k++) {
                const float a0 = hidc[(r0 + 0) * HP + ksub * 48 + k];
                const float a1 = hidc[(r0 + 1) * HP + ksub * 48 + k];
                const float a2 = hidc[(r0 + 2) * HP + ksub * 48 + k];
                const float a3 = hidc[(r0 + 3) * HP + ksub * 48 + k];
                const float* wr = &ws[k * 96 + c0];
                #pragma unroll
                for (int j = 0; j < 6; j++) {
                    const float w = wr[j];
                    acc[0][j] += a0 * w;
                    acc[1][j] += a1 * w;
                    acc[2][j] += a2 * w;
                    acc[3][j] += a3 * w;
                }
            }
            __syncthreads();
        }
    }

    // Epilogue: out = x1 + mlp_out + b2
    const int c0 = cgO * 6;
    #pragma unroll
    for (int i = 0; i < 4; i++) {
        const int tt = t0 + r0 + i;
        const float* xr = g_x1 + tt * 96 + c0;
        float* orow = out + tt * 96 + c0;
        #pragma unroll
        for (int j = 0; j < 6; j++)
            orow[j] = xr[j] + acc[i][j] + b2m[c0 + j];
    }
}

// ---------------------------------------------------------------------------
extern "C" void kernel_launch(void* const* d_in, const int* in_sizes, int n_in,
                              void* d_out, int out_size)
{
    (void)in_sizes; (void)n_in; (void)out_size;
    const float* x     = (const float*)d_in[0];
    const float* n1g   = (const float*)d_in[1];
    const float* n1b   = (const float*)d_in[2];
    const float* qkvw  = (const float*)d_in[3];
    const float* qkvb  = (const float*)d_in[4];
    const float* projw = (const float*)d_in[5];
    const float* projb = (const float*)d_in[6];
    const float* btab  = (const float*)d_in[7];
    const float* n2g   = (const float*)d_in[8];
    const float* n2b   = (const float*)d_in[9];
    const float* w1    = (const float*)d_in[10];
    const float* b1m   = (const float*)d_in[11];
    const float* w2    = (const float*)d_in[12];
    const float* b2m   = (const float*)d_in[13];
    float* out = (float*)d_out;

    k1_ln_qkv<<<NWIN, 128>>>(x, n1g, n1b, qkvw, qkvb);
    k2_attn  <<<NWIN * 6, 64>>>(btab);
    k3_proj  <<<NWIN, 128>>>(x, projw, projb);
    k4_mlp   <<<NTOK / 32, 128>>>(n2g, n2b, w1, b1m, w2, b2m, out);
}

// round 3
// speedup vs baseline: 1.0634x; 1.0634x over previous
#include <cuda_runtime.h>

// ---------------------------------------------------------------------------
// SwinTransformerBlock3D: DIM=96, HEADS=6, hd=16, WIN=4x4x4 (N=64), SHIFT=2,
// GRID=(16,64,64), B=2.  Cyclic shift == index remap (no mask in reference).
// f32x2 packed-FMA inner loops (2 MAC / issue slot on sm_103a).
// ---------------------------------------------------------------------------

#define NWIN 2048
#define NTOK 131072
#define DIMC 96
#define HP 97

typedef unsigned long long u64;

__device__ __forceinline__ u64 pk2(float x, float y) {
    u64 r;
    asm("mov.b64 %0, {%1, %2};" : "=l"(r)
        : "r"(__float_as_uint(x)), "r"(__float_as_uint(y)));
    return r;
}
__device__ __forceinline__ void upk2(u64 v, float& x, float& y) {
    unsigned int a, b;
    asm("mov.b64 {%0, %1}, %2;" : "=r"(a), "=r"(b) : "l"(v));
    x = __uint_as_float(a); y = __uint_as_float(b);
}
__device__ __forceinline__ void fma2(u64& d, u64 a, u64 b) {
    asm("fma.rn.f32x2 %0, %1, %2, %0;" : "+l"(d) : "l"(a), "l"(b));
}
__device__ __forceinline__ void add2(u64& d, u64 a, u64 b) {
    asm("add.rn.f32x2 %0, %1, %2;" : "=l"(d) : "l"(a), "l"(b));
}

// Scratch
__device__ float g_q [NWIN * 64 * DIMC];
__device__ float g_k [NWIN * 64 * DIMC];
__device__ float g_v [NWIN * 64 * DIMC];
__device__ float g_ow[NWIN * 64 * DIMC];
__device__ float g_x1[NTOK * DIMC];

// ---------------------------------------------------------------------------
// K1: LN1 + shift gather + QKV GEMM (64x288, K=96). 1 block/window, 128 thr.
// ---------------------------------------------------------------------------
__global__ __launch_bounds__(128) void k1_ln_qkv(
    const float* __restrict__ x,
    const float* __restrict__ g1, const float* __restrict__ b1,
    const float* __restrict__ qkvw, const float* __restrict__ qkvb)
{
    __shared__ float hs[64 * HP];
    __shared__ float ws[96 * 48];

    const int tid  = threadIdx.x;
    const int lane = tid & 31;
    const int wrp  = tid >> 5;
    const int win  = blockIdx.x;
    const int b  = win >> 10;
    const int r  = win & 1023;
    const int wi = r >> 8, wx = (r >> 4) & 15, wt = r & 15;

    const float gv0 = g1[lane], gv1 = g1[lane + 32], gv2 = g1[lane + 64];
    const float bb0 = b1[lane], bb1 = b1[lane + 32], bb2 = b1[lane + 64];

    for (int j = 0; j < 16; j++) {
        const int n  = wrp * 16 + j;
        const int ii = n >> 4, xx = (n >> 2) & 3, tt = n & 3;
        const int gi = (wi * 4 + ii + 2) & 15;
        const int gx = (wx * 4 + xx + 2) & 63;
        const int gt = (wt * 4 + tt + 2) & 63;
        const int tok = b * 65536 + (gi * 64 + gx) * 64 + gt;
        const float* row = x + tok * 96;
        float v0 = row[lane], v1 = row[lane + 32], v2 = row[lane + 64];
        float s = v0 + v1 + v2;
        float q = v0 * v0 + v1 * v1 + v2 * v2;
        #pragma unroll
        for (int o = 16; o > 0; o >>= 1) {
            s += __shfl_xor_sync(0xffffffffu, s, o);
            q += __shfl_xor_sync(0xffffffffu, q, o);
        }
        const float mean = s * (1.0f / 96.0f);
        const float var  = q * (1.0f / 96.0f) - mean * mean;
        const float rstd = rsqrtf(var + 1e-5f);
        hs[n * HP + lane]      = (v0 - mean) * rstd * gv0 + bb0;
        hs[n * HP + lane + 32] = (v1 - mean) * rstd * gv1 + bb1;
        hs[n * HP + lane + 64] = (v2 - mean) * rstd * gv2 + bb2;
    }
    __syncthreads();

    const int rg = tid >> 3;   // 16 groups x 4 rows
    const int cg = tid & 7;    // 8 groups x 6 cols
    const int r0 = rg * 4, c0 = cg * 6;

    for (int cc = 0; cc < 6; cc++) {
        const int colbase = cc * 48;
        for (int idx = tid; idx < 1152; idx += 128) {
            const int row = idx / 12, c4 = idx % 12;
            *(float4*)&ws[row * 48 + c4 * 4] =
                *(const float4*)(qkvw + row * 288 + colbase + c4 * 4);
        }
        __syncthreads();

        u64 acc[4][3];
        #pragma unroll
        for (int i = 0; i < 4; i++)
            #pragma unroll
            for (int j = 0; j < 3; j++) acc[i][j] = 0ull;

        #pragma unroll 4
        for (int k = 0; k < 96; k++) {
            const u64 p0 = pk2(hs[(r0 + 0) * HP + k], hs[(r0 + 0) * HP + k]);
            const u64 p1 = pk2(hs[(r0 + 1) * HP + k], hs[(r0 + 1) * HP + k]);
            const u64 p2 = pk2(hs[(r0 + 2) * HP + k], hs[(r0 + 2) * HP + k]);
            const u64 p3 = pk2(hs[(r0 + 3) * HP + k], hs[(r0 + 3) * HP + k]);
            const u64* wr = (const u64*)&ws[k * 48 + c0];
            const u64 b0 = wr[0], b1v = wr[1], b2v = wr[2];
            fma2(acc[0][0], p0, b0); fma2(acc[0][1], p0, b1v); fma2(acc[0][2], p0, b2v);
            fma2(acc[1][0], p1, b0); fma2(acc[1][1], p1, b1v); fma2(acc[1][2], p1, b2v);
            fma2(acc[2][0], p2, b0); fma2(acc[2][1], p2, b1v); fma2(acc[2][2], p2, b2v);
            fma2(acc[3][0], p3, b0); fma2(acc[3][1], p3, b1v); fma2(acc[3][2], p3, b2v);
        }

        float* dst = (cc < 2) ? g_q : (cc < 4) ? g_k : g_v;
        const int cb = (cc & 1) * 48;
        #pragma unroll
        for (int i = 0; i < 4; i++) {
            float* drow = dst + (win * 64 + r0 + i) * 96 + cb + c0;
            #pragma unroll
            for (int jp = 0; jp < 3; jp++) {
                float ax, ay; upk2(acc[i][jp], ax, ay);
                drow[2 * jp]     = ax + qkvb[colbase + c0 + 2 * jp];
                drow[2 * jp + 1] = ay + qkvb[colbase + c0 + 2 * jp + 1];
            }
        }
        __syncthreads();
    }
}

// ---------------------------------------------------------------------------
// K2: windowed attention, 1 block/(window,head), 64 threads.
// ---------------------------------------------------------------------------
__global__ __launch_bounds__(64) void k2_attn(const float* __restrict__ btab)
{
    __shared__ float sq[64 * 16], sk[64 * 16], sv[64 * 16];
    __shared__ float ss[64 * 65];
    __shared__ float stab[343 * 6];

    const int n    = threadIdx.x;
    const int win  = blockIdx.x / 6;
    const int head = blockIdx.x % 6;
    const int base = win * 64 * 96 + head * 16;

    #pragma unroll
    for (int j = 0; j < 4; j++) {
        ((float4*)sq)[n * 4 + j] = ((const float4*)(g_q + base + n * 96))[j];
        ((float4*)sk)[n * 4 + j] = ((const float4*)(g_k + base + n * 96))[j];
        ((float4*)sv)[n * 4 + j] = ((const float4*)(g_v + base + n * 96))[j];
    }
    for (int i = n; i < 2058; i += 64) stab[i] = btab[i];
    __syncthreads();

    u64 qp[8];
    {
        const u64* qq = (const u64*)(sq + n * 16);
        #pragma unroll
        for (int j = 0; j < 8; j++) qp[j] = qq[j];
    }
    const int iin = n >> 4, xn = (n >> 2) & 3, tn = n & 3;
    float* myrow = &ss[n * 65];

    #pragma unroll 8
    for (int m = 0; m < 64; m++) {
        const ulonglong2* kp = (const ulonglong2*)(sk + m * 16);
        u64 sa = 0ull, sb = 0ull;
        #pragma unroll
        for (int j = 0; j < 4; j++) {
            const ulonglong2 kv = kp[j];
            fma2(sa, qp[2 * j],     kv.x);
            fma2(sb, qp[2 * j + 1], kv.y);
        }
        u64 st; add2(st, sa, sb);
        float sx, sy; upk2(st, sx, sy);
        const float s = sx + sy;
        const int im = m >> 4, xm = (m >> 2) & 3, tm = m & 3;
        const int rel = ((iin - im + 3) * 7 + (xn - xm + 3)) * 7 + (tn - tm + 3);
        myrow[m] = s * 0.25f + stab[rel * 6 + head];
    }

    float mx = -1e30f;
    #pragma unroll
    for (int m = 0; m < 64; m++) mx = fmaxf(mx, myrow[m]);
    float sum = 0.0f;
    #pragma unroll 8
    for (int m = 0; m < 64; m++) {
        const float p = __expf(myrow[m] - mx);
        myrow[m] = p;
        sum += p;
    }
    const float inv = 1.0f / sum;

    u64 ov[8];
    #pragma unroll
    for (int j = 0; j < 8; j++) ov[j] = 0ull;
    #pragma unroll 8
    for (int m = 0; m < 64; m++) {
        const float p = myrow[m];
        const u64 pp = pk2(p, p);
        const ulonglong2* vp = (const ulonglong2*)(sv + m * 16);
        #pragma unroll
        for (int j = 0; j < 4; j++) {
            const ulonglong2 vv = vp[j];
            fma2(ov[2 * j],     pp, vv.x);
            fma2(ov[2 * j + 1], pp, vv.y);
        }
    }
    float* od = g_ow + base + n * 96;
    #pragma unroll
    for (int j = 0; j < 8; j++) {
        float oxv, oyv; upk2(ov[j], oxv, oyv);
        od[2 * j]     = oxv * inv;
        od[2 * j + 1] = oyv * inv;
    }
}

// ---------------------------------------------------------------------------
// K3: proj GEMM + window reverse + un-shift scatter + residual.
// ---------------------------------------------------------------------------
__global__ __launch_bounds__(128) void k3_proj(
    const float* __restrict__ x,
    const float* __restrict__ pw, const float* __restrict__ pb)
{
    __shared__ float os[64 * HP];
    __shared__ float ws[96 * 48];

    const int tid = threadIdx.x;
    const int win = blockIdx.x;

    for (int idx = tid; idx < 1536; idx += 128) {
        const float4 v = ((const float4*)(g_ow + win * 64 * 96))[idx];
        const int row = idx / 24, c4 = idx % 24;
        float* d = &os[row * HP + c4 * 4];
        d[0] = v.x; d[1] = v.y; d[2] = v.z; d[3] = v.w;
    }

    const int b = win >> 10, r = win & 1023;
    const int wi = r >> 8, wx = (r >> 4) & 15, wt = r & 15;
    const int rg = tid >> 3, cg = tid & 7;
    const int r0 = rg * 4, c0 = cg * 6;

    int tok[4];
    #pragma unroll
    for (int i = 0; i < 4; i++) {
        const int n = r0 + i;
        const int ii = n >> 4, xx = (n >> 2) & 3, tt = n & 3;
        const int gi = (wi * 4 + ii + 2) & 15;
        const int gx = (wx * 4 + xx + 2) & 63;
        const int gt = (wt * 4 + tt + 2) & 63;
        tok[i] = b * 65536 + (gi * 64 + gx) * 64 + gt;
    }
    __syncthreads();

    for (int cc = 0; cc < 2; cc++) {
        const int colbase = cc * 48;
        for (int idx = tid; idx < 1152; idx += 128) {
            const int row = idx / 12, c4 = idx % 12;
            *(float4*)&ws[row * 48 + c4 * 4] =
                *(const float4*)(pw + row * 96 + colbase + c4 * 4);
        }
        __syncthreads();

        u64 acc[4][3];
        #pragma unroll
        for (int i = 0; i < 4; i++)
            #pragma unroll
            for (int j = 0; j < 3; j++) acc[i][j] = 0ull;

        #pragma unroll 4
        for (int k = 0; k < 96; k++) {
            const u64 p0 = pk2(os[(r0 + 0) * HP + k], os[(r0 + 0) * HP + k]);
            const u64 p1 = pk2(os[(r0 + 1) * HP + k], os[(r0 + 1) * HP + k]);
            const u64 p2 = pk2(os[(r0 + 2) * HP + k], os[(r0 + 2) * HP + k]);
            const u64 p3 = pk2(os[(r0 + 3) * HP + k], os[(r0 + 3) * HP + k]);
            const u64* wr = (const u64*)&ws[k * 48 + c0];
            const u64 b0 = wr[0], b1v = wr[1], b2v = wr[2];
            fma2(acc[0][0], p0, b0); fma2(acc[0][1], p0, b1v); fma2(acc[0][2], p0, b2v);
            fma2(acc[1][0], p1, b0); fma2(acc[1][1], p1, b1v); fma2(acc[1][2], p1, b2v);
            fma2(acc[2][0], p2, b0); fma2(acc[2][1], p2, b1v); fma2(acc[2][2], p2, b2v);
            fma2(acc[3][0], p3, b0); fma2(acc[3][1], p3, b1v); fma2(acc[3][2], p3, b2v);
        }

        #pragma unroll
        for (int i = 0; i < 4; i++) {
            const float* xr = x + tok[i] * 96 + colbase + c0;
            float* dr = g_x1 + tok[i] * 96 + colbase + c0;
            #pragma unroll
            for (int jp = 0; jp < 3; jp++) {
                float ax, ay; upk2(acc[i][jp], ax, ay);
                dr[2 * jp]     = xr[2 * jp]     + ax + pb[colbase + c0 + 2 * jp];
                dr[2 * jp + 1] = xr[2 * jp + 1] + ay + pb[colbase + c0 + 2 * jp + 1];
            }
        }
        __syncthreads();
    }
}

// ---------------------------------------------------------------------------
// K4: LN2 + MLP + residual. 64 tokens/block, 128 threads, dynamic smem.
// layout: xs[64*HP] | hidc[64*HP] | ws[4608]
// ---------------------------------------------------------------------------
#define K4_SMEM_FLOATS (2 * 64 * HP + 96 * 48)

__global__ __launch_bounds__(128) void k4_mlp(
    const float* __restrict__ g2, const float* __restrict__ b2,
    const float* __restrict__ w1, const float* __restrict__ b1m,
    const float* __restrict__ w2, const float* __restrict__ b2m,
    float* __restrict__ out)
{
    extern __shared__ float dsm[];
    float* xs   = dsm;
    float* hidc = dsm + 64 * HP;
    float* ws   = dsm + 2 * 64 * HP;

    const int tid  = threadIdx.x;
    const int lane = tid & 31;
    const int wrp  = tid >> 5;
    const int t0   = blockIdx.x * 64;

    const float gv0 = g2[lane], gv1 = g2[lane + 32], gv2 = g2[lane + 64];
    const float bb0 = b2[lane], bb1 = b2[lane + 32], bb2 = b2[lane + 64];

    for (int j = 0; j < 16; j++) {
        const int rrow = wrp * 16 + j;
        const float* row = g_x1 + (t0 + rrow) * 96;
        float v0 = row[lane], v1 = row[lane + 32], v2 = row[lane + 64];
        float s = v0 + v1 + v2;
        float q = v0 * v0 + v1 * v1 + v2 * v2;
        #pragma unroll
        for (int o = 16; o > 0; o >>= 1) {
            s += __shfl_xor_sync(0xffffffffu, s, o);
            q += __shfl_xor_sync(0xffffffffu, q, o);
        }
        const float mean = s * (1.0f / 96.0f);
        const float var  = q * (1.0f / 96.0f) - mean * mean;
        const float rstd = rsqrtf(var + 1e-5f);
        xs[rrow * HP + lane]      = (v0 - mean) * rstd * gv0 + bb0;
        xs[rrow * HP + lane + 32] = (v1 - mean) * rstd * gv1 + bb1;
        xs[rrow * HP + lane + 64] = (v2 - mean) * rstd * gv2 + bb2;
    }
    __syncthreads();

    // phase A tiling: 16 row-groups x 4, 8 col-groups x 6 (48-col chunks)
    const int rA = (tid >> 3) * 4, cA = (tid & 7) * 6;
    // phase B tiling: 8 row-groups x 8, 16 col-groups x 6 (96 cols)
    const int rB = (tid >> 4) * 8, cB = (tid & 15) * 6;

    u64 acc[8][3];
    #pragma unroll
    for (int i = 0; i < 8; i++)
        #pragma unroll
        for (int j = 0; j < 3; j++) acc[i][j] = 0ull;

    for (int hc = 0; hc < 4; hc++) {
        // Phase A: hidc[64][96] = gelu(xs @ w1_chunk + b1)
        for (int sub = 0; sub < 2; sub++) {
            const int hbase = hc * 96 + sub * 48;
            for (int idx = tid; idx < 1152; idx += 128) {
                const int row = idx / 12, c4 = idx % 12;
                *(float4*)&ws[row * 48 + c4 * 4] =
                    *(const float4*)(w1 + row * 384 + hbase + c4 * 4);
            }
            __syncthreads();

            u64 ah[4][3];
            #pragma unroll
            for (int i = 0; i < 4; i++)
                #pragma unroll
                for (int j = 0; j < 3; j++) ah[i][j] = 0ull;

            #pragma unroll 4
            for (int k = 0; k < 96; k++) {
                const u64 p0 = pk2(xs[(rA + 0) * HP + k], xs[(rA + 0) * HP + k]);
                const u64 p1 = pk2(xs[(rA + 1) * HP + k], xs[(rA + 1) * HP + k]);
                const u64 p2 = pk2(xs[(rA + 2) * HP + k], xs[(rA + 2) * HP + k]);
                const u64 p3 = pk2(xs[(rA + 3) * HP + k], xs[(rA + 3) * HP + k]);
                const u64* wr = (const u64*)&ws[k * 48 + cA];
                const u64 b0 = wr[0], b1v = wr[1], b2v = wr[2];
                fma2(ah[0][0], p0, b0); fma2(ah[0][1], p0, b1v); fma2(ah[0][2], p0, b2v);
                fma2(ah[1][0], p1, b0); fma2(ah[1][1], p1, b1v); fma2(ah[1][2], p1, b2v);
                fma2(ah[2][0], p2, b0); fma2(ah[2][1], p2, b1v); fma2(ah[2][2], p2, b2v);
                fma2(ah[3][0], p3, b0); fma2(ah[3][1], p3, b1v); fma2(ah[3][2], p3, b2v);
            }
            #pragma unroll
            for (int i = 0; i < 4; i++)
                #pragma unroll
                for (int jp = 0; jp < 3; jp++) {
                    float hx, hy; upk2(ah[i][jp], hx, hy);
                    hx += b1m[hbase + cA + 2 * jp];
                    hy += b1m[hbase + cA + 2 * jp + 1];
                    hidc[(i + rA) * HP + sub * 48 + cA + 2 * jp] =
                        0.5f * hx * (1.0f + erff(hx * 0.70710678118654752f));
                    hidc[(i + rA) * HP + sub * 48 + cA + 2 * jp + 1] =
                        0.5f * hy * (1.0f + erff(hy * 0.70710678118654752f));
                }
            __syncthreads();
        }

        // Phase B: acc += hidc @ w2_chunk
        for (int ksub = 0; ksub < 2; ksub++) {
            const int kb = hc * 96 + ksub * 48;
            for (int idx = tid; idx < 1152; idx += 128) {
                const int row = idx / 24, c4 = idx % 24;
                *(float4*)&ws[row * 96 + c4 * 4] =
                    *(const float4*)(w2 + (kb + row) * 96 + c4 * 4);
            }
            __syncthreads();

            #pragma unroll 2
            for (int k = 0; k < 48; k++) {
                const u64* wr = (const u64*)&ws[k * 96 + cB];
                const u64 b0 = wr[0], b1v = wr[1], b2v = wr[2];
                #pragma unroll
                for (int i = 0; i < 8; i++) {
                    const float a = hidc[(rB + i) * HP + ksub * 48 + k];
                    const u64 pa = pk2(a, a);
                    fma2(acc[i][0], pa, b0);
                    fma2(acc[i][1], pa, b1v);
                    fma2(acc[i][2], pa, b2v);
                }
            }
            __syncthreads();
        }
    }

    // Epilogue: out = x1 + mlp_out + b2m
    #pragma unroll
    for (int i = 0; i < 8; i++) {
        const int tt = t0 + rB + i;
        const float* xr = g_x1 + tt * 96 + cB;
        float* orow = out + tt * 96 + cB;
        #pragma unroll
        for (int jp = 0; jp < 3; jp++) {
            float ax, ay; upk2(acc[i][jp], ax, ay);
            orow[2 * jp]     = xr[2 * jp]     + ax + b2m[cB + 2 * jp];
            orow[2 * jp + 1] = xr[2 * jp + 1] + ay + b2m[cB + 2 * jp + 1];
        }
    }
}

// ---------------------------------------------------------------------------
extern "C" void kernel_launch(void* const* d_in, const int* in_sizes, int n_in,
                              void* d_out, int out_size)
{
    (void)in_sizes; (void)n_in; (void)out_size;
    const float* x     = (const float*)d_in[0];
    const float* n1g   = (const float*)d_in[1];
    const float* n1b   = (const float*)d_in[2];
    const float* qkvw  = (const float*)d_in[3];
    const float* qkvb  = (const float*)d_in[4];
    const float* projw = (const float*)d_in[5];
    const float* projb = (const float*)d_in[6];
    const float* btab  = (const float*)d_in[7];
    const float* n2g   = (const float*)d_in[8];
    const float* n2b   = (const float*)d_in[9];
    const float* w1    = (const float*)d_in[10];
    const float* b1m   = (const float*)d_in[11];
    const float* w2    = (const float*)d_in[12];
    const float* b2m   = (const float*)d_in[13];
    float* out = (float*)d_out;

    const int k4_smem = K4_SMEM_FLOATS * (int)sizeof(float);
    cudaFuncSetAttribute(k4_mlp, cudaFuncAttributeMaxDynamicSharedMemorySize, k4_smem);

    k1_ln_qkv<<<NWIN, 128>>>(x, n1g, n1b, qkvw, qkvb);
    k2_attn  <<<NWIN * 6, 64>>>(btab);
    k3_proj  <<<NWIN, 128>>>(x, projw, projb);
    k4_mlp   <<<NTOK / 64, 128, k4_smem>>>(n2g, n2b, w1, b1m, w2, b2m, out);
}